// round 8
// baseline (speedup 1.0000x reference)
#include <cuda_runtime.h>
#include <cuda_fp16.h>
#include <cstdint>

#define NTOK 4096
#define DIM  1024
#define HID  2048
#define NEXP 8
#define VOC  32000
#define LN_EPS 1e-5f
#define GEMM_SMEM (1024 + 3 * 32 * 1024)   // rows[]/pad + 3 stages * (A 16K + B 16K)

// fused-grid block counts
#define G1_BLOCKS   (16 * 32 * 8)                       // GEMM1 tiles
#define W2T_BLOCKS  ((DIM / 32) * (HID / 32) * NEXP)    // 16384 W2-transpose tiles
#define CH_BLOCKS   512                                 // head_W fp32->fp16 grid-stride
#define W1T_BLOCKS  ((HID / 32) * (DIM / 32) * NEXP)    // 16384 W1-transpose tiles

// ---------------- device-global scratch ----------------
__device__ __half g_hh [(size_t)NTOK * DIM];            // embeddings fp16
__device__ __half g_ah [(size_t)NTOK * 2 * HID];        // expert act fp16 per slot
__device__ float  g_eo [(size_t)NTOK * 2 * DIM];        // expert out fp32 per slot
__device__ __half g_ynh[(size_t)NTOK * DIM];            // layernormed fp16
__device__ __half g_Whf[(size_t)VOC * DIM];             // head_W fp16
__device__ __half g_W1h[(size_t)NEXP * HID * DIM];      // W1^T fp16 [E][N][K]
__device__ __half g_W2h[(size_t)NEXP * DIM * HID];      // W2^T fp16 [E][N][K]
__device__ float g_tv[NTOK * 2];
__device__ int   g_list[NEXP * NTOK];
__device__ int   g_count[NEXP];

// ---------------- helpers ----------------
__device__ __forceinline__ uint32_t sw128(uint32_t o) { return o ^ ((o >> 3) & 0x70); }
__device__ __forceinline__ void cpa16(uint32_t d, const void* s) {
    asm volatile("cp.async.cg.shared.global [%0], [%1], 16;" :: "r"(d), "l"(s));
}
__device__ __forceinline__ void ldmx4(uint32_t* r, uint32_t a) {
    asm volatile("ldmatrix.sync.aligned.m8n8.x4.shared.b16 {%0,%1,%2,%3}, [%4];"
                 : "=r"(r[0]), "=r"(r[1]), "=r"(r[2]), "=r"(r[3]) : "r"(a));
}
__device__ __forceinline__ void mma_hf(float* c, const uint32_t* a, const uint32_t* b) {
    asm volatile("mma.sync.aligned.m16n8k16.row.col.f32.f16.f16.f32 "
                 "{%0,%1,%2,%3},{%4,%5,%6,%7},{%8,%9},{%0,%1,%2,%3};"
                 : "+f"(c[0]), "+f"(c[1]), "+f"(c[2]), "+f"(c[3])
                 : "r"(a[0]), "r"(a[1]), "r"(a[2]), "r"(a[3]), "r"(b[0]), "r"(b[1]));
}

__global__ void reset_counts_kernel() { if (threadIdx.x < NEXP) g_count[threadIdx.x] = 0; }

// ---------------- kernel: embed + gate + top2 + scatter, fused with W1 transpose ----------------
// blocks [0, NTOK): embed/gate; blocks [NTOK, NTOK+W1T_BLOCKS): W1 [E][K][N]->fp16 [E][N][K]
__global__ void embed_gate_w1_kernel(const int* __restrict__ x,
                                     const float* __restrict__ embed_W,
                                     const float* __restrict__ gate_W,
                                     const float* __restrict__ gate_b,
                                     const float* __restrict__ W1,
                                     float* __restrict__ out, int write_idx) {
    __shared__ union {
        struct { float sh[DIM]; float slogit[NEXP]; } eg;
        float t[32][33];
    } u;
    const int bid = blockIdx.x, tid = threadIdx.x;

    if (bid >= NTOK) {                                  // ---- W1 transpose tile ----
        const int t = bid - NTOK;                       // K=DIM, N=HID
        const int e = t >> 11;                          // (HID/32)*(DIM/32)=2048 per expert
        const int r = t & 2047;
        const int nb = (r & 63) * 32;                   // N tiles: HID/32=64
        const int kb = (r >> 6) * 32;                   // K tiles: DIM/32=32
        const float* pin = W1 + (size_t)e * DIM * HID;
        __half* ph = g_W1h + (size_t)e * DIM * HID;
        const int tx = tid & 31, ty = tid >> 5;
        #pragma unroll
        for (int i = 0; i < 32; i += 8)
            u.t[ty + i][tx] = pin[(size_t)(kb + ty + i) * HID + nb + tx];
        __syncthreads();
        #pragma unroll
        for (int i = 0; i < 32; i += 8)
            ph[(size_t)(nb + ty + i) * DIM + kb + tx] = __float2half(u.t[tx][ty + i]);
        return;
    }

    const int n = bid;
    const float* erow = embed_W + (size_t)x[n] * DIM;
    #pragma unroll
    for (int q = 0; q < DIM / 256; ++q) {
        int d = tid + q * 256;
        float v = erow[d];
        u.eg.sh[d] = v;
        g_hh[(size_t)n * DIM + d] = __float2half(v);
    }
    __syncthreads();
    const int w = tid >> 5, lane = tid & 31;
    const float* gw = gate_W + (size_t)w * DIM;
    float acc = 0.f;
    for (int d = lane; d < DIM; d += 32) acc = fmaf(u.eg.sh[d], gw[d], acc);
    #pragma unroll
    for (int o = 16; o > 0; o >>= 1) acc += __shfl_xor_sync(0xffffffffu, acc, o);
    if (lane == 0) u.eg.slogit[w] = acc + gate_b[w];
    __syncthreads();
    if (tid == 0) {
        float mx = u.eg.slogit[0];
        #pragma unroll
        for (int e = 1; e < NEXP; ++e) mx = fmaxf(mx, u.eg.slogit[e]);
        float p[NEXP], s = 0.f;
        #pragma unroll
        for (int e = 0; e < NEXP; ++e) { p[e] = expf(u.eg.slogit[e] - mx); s += p[e]; }
        float inv = 1.f / s;
        #pragma unroll
        for (int e = 0; e < NEXP; ++e) p[e] *= inv;
        int i0 = 0; float v0 = p[0];
        #pragma unroll
        for (int e = 1; e < NEXP; ++e) if (p[e] > v0) { v0 = p[e]; i0 = e; }
        int i1 = -1; float v1 = -1.f;
        #pragma unroll
        for (int e = 0; e < NEXP; ++e) {
            if (e != i0 && p[e] > v1) { v1 = p[e]; i1 = e; }
        }
        g_tv[n*2+0] = v0; g_tv[n*2+1] = v1;
        int p0 = atomicAdd(&g_count[i0], 1); g_list[i0 * NTOK + p0] = n*2;
        int p1 = atomicAdd(&g_count[i1], 1); g_list[i1 * NTOK + p1] = n*2+1;
        if (write_idx) {
            out[(size_t)NTOK * VOC + n*2+0] = (float)i0;
            out[(size_t)NTOK * VOC + n*2+1] = (float)i1;
        }
    }
}

// ---------------- GEMM1 (fp16, relu(h W1+b1) -> g_ah), fused with W2 transpose + head_W conv ----------------
__global__ void __launch_bounds__(256, 2) gemm1_fused_kernel(const float* __restrict__ b1,
                                                             const float* __restrict__ W2,
                                                             const float4* __restrict__ Wh) {
    constexpr int KTOT = DIM, NTOT = HID, NCHUNK = KTOT / 64;
    extern __shared__ char smem[];
    const int bid = blockIdx.x, tid = threadIdx.x;

    if (bid >= G1_BLOCKS + W2T_BLOCKS) {                // ---- head_W fp32->fp16 ----
        long i = (long)(bid - G1_BLOCKS - W2T_BLOCKS) * 256 + tid;
        const long n4 = (long)VOC * DIM / 4;
        const long stride = (long)CH_BLOCKS * 256;
        __half2* o = (__half2*)g_Whf;
        for (; i < n4; i += stride) {
            float4 v = Wh[i];
            o[i*2+0] = __floats2half2_rn(v.x, v.y);
            o[i*2+1] = __floats2half2_rn(v.z, v.w);
        }
        return;
    }
    if (bid >= G1_BLOCKS) {                             // ---- W2 transpose tile ----
        float (*t)[33] = (float(*)[33])smem;            // K=HID, N=DIM
        const int tt = bid - G1_BLOCKS;
        const int e = tt >> 11;                         // (DIM/32)*(HID/32)=2048 per expert
        const int r = tt & 2047;
        const int nb = (r & 31) * 32;                   // N tiles: DIM/32=32
        const int kb = (r >> 5) * 32;                   // K tiles: HID/32=64
        const float* pin = W2 + (size_t)e * HID * DIM;
        __half* ph = g_W2h + (size_t)e * HID * DIM;
        const int tx = tid & 31, ty = tid >> 5;
        #pragma unroll
        for (int i = 0; i < 32; i += 8)
            t[ty + i][tx] = pin[(size_t)(kb + ty + i) * DIM + nb + tx];
        __syncthreads();
        #pragma unroll
        for (int i = 0; i < 32; i += 8)
            ph[(size_t)(nb + ty + i) * HID + kb + tx] = __float2half(t[tx][ty + i]);
        return;
    }

    // ---- GEMM1 tile: e = bid/512, mt = (bid%512)/16, nt = bid%16 ----
    const int e = bid >> 9, mt = (bid >> 4) & 31, nt = bid & 15;
    if (mt * 128 >= g_count[e]) return;
    const int rowBase = mt * 128, nBase = nt * 128;
    const uint32_t sb = (uint32_t)__cvta_generic_to_shared(smem);
    int* rows = (int*)smem;
    if (tid < 128) {
        int r = rowBase + tid;
        rows[tid] = (r < g_count[e]) ? g_list[e * NTOK + r] : -1;
    }
    __syncthreads();

    const __half* A = g_hh;
    const __half* B = g_W1h + (size_t)e * KTOT * NTOT + (size_t)nBase * KTOT;

    auto load_stage = [&](int st, int chunk) {
        const uint32_t stb = sb + 1024 + st * 32768;
        const int k0 = chunk * 64;
        #pragma unroll
        for (int t = 0; t < 4; ++t) {
            int c = tid + t * 256, r = c >> 3, q = c & 7;
            int s = rows[r]; if (s < 0) s = rows[0];
            size_t ro = (size_t)(s >> 1) * KTOT + k0 + q * 8;
            uint32_t so = sw128((uint32_t)(r * 128 + q * 16));
            cpa16(stb + so,         A + ro);
            cpa16(stb + 16384 + so, B + (size_t)r * KTOT + k0 + q * 8);
        }
    };

    const int lane = tid & 31, wid = tid >> 5;
    const int wm = (wid & 3) * 32, wn = (wid >> 2) * 64;
    const uint32_t aoff = (uint32_t)((wm + (lane & 15)) * 128 + (lane >> 4) * 16);
    const uint32_t boff0 = (uint32_t)((wn + ((lane >> 4) << 3) + (lane & 7)) * 128 +
                                      ((lane >> 3) & 1) * 16);

    float acc[2][8][4];
    #pragma unroll
    for (int i = 0; i < 2; ++i)
        #pragma unroll
        for (int j = 0; j < 8; ++j)
            #pragma unroll
            for (int k = 0; k < 4; ++k) acc[i][j][k] = 0.f;

    load_stage(0, 0); asm volatile("cp.async.commit_group;");
    load_stage(1, 1); asm volatile("cp.async.commit_group;");

    for (int it = 0; it < NCHUNK; ++it) {
        const int st = it % 3;
        asm volatile("cp.async.wait_group 1;");
        __syncthreads();
        const uint32_t stb = sb + 1024 + st * 32768;
        #pragma unroll
        for (int ks = 0; ks < 4; ++ks) {
            const uint32_t kb = ks * 32;
            uint32_t a[2][4], b[8][2];
            #pragma unroll
            for (int mi = 0; mi < 2; ++mi)
                ldmx4(a[mi], stb + sw128(aoff + mi * 16 * 128 + kb));
            #pragma unroll
            for (int nj = 0; nj < 4; ++nj) {
                uint32_t r[4];
                ldmx4(r, stb + 16384 + sw128(boff0 + nj * 16 * 128 + kb));
                b[nj*2][0] = r[0]; b[nj*2][1] = r[1];
                b[nj*2+1][0] = r[2]; b[nj*2+1][1] = r[3];
            }
            #pragma unroll
            for (int mi = 0; mi < 2; ++mi)
                #pragma unroll
                for (int nf = 0; nf < 8; ++nf)
                    mma_hf(acc[mi][nf], a[mi], b[nf]);
        }
        if (it + 2 < NCHUNK) load_stage((it + 2) % 3, it + 2);
        asm volatile("cp.async.commit_group;");
    }

    #pragma unroll
    for (int mi = 0; mi < 2; ++mi) {
        #pragma unroll
        for (int h = 0; h < 2; ++h) {
            const int rl = wm + mi * 16 + (lane >> 2) + h * 8;
            const int slot = rows[rl];
            if (slot < 0) continue;
            #pragma unroll
            for (int nf = 0; nf < 8; ++nf) {
                const int gc = nBase + wn + nf * 8 + (lane & 3) * 2;
                float a0 = acc[mi][nf][h*2]   + b1[(size_t)e * HID + gc];
                float a1 = acc[mi][nf][h*2+1] + b1[(size_t)e * HID + gc + 1];
                a0 = a0 > 0.f ? a0 : 0.f;
                a1 = a1 > 0.f ? a1 : 0.f;
                *(__half2*)(g_ah + (size_t)slot * HID + gc) = __floats2half2_rn(a0, a1);
            }
        }
    }
}

// ---------------- GEMM2 (fp16, a W2 + b2 -> g_eo fp32) ----------------
__global__ void __launch_bounds__(256, 2) gemm2_kernel(const float* __restrict__ b2) {
    constexpr int KTOT = HID, NTOT = DIM, NCHUNK = KTOT / 64;
    extern __shared__ char smem[];
    const int tid = threadIdx.x;
    const int mt = blockIdx.y, nt = blockIdx.x, e = blockIdx.z;
    if (mt * 128 >= g_count[e]) return;
    const int rowBase = mt * 128, nBase = nt * 128;
    const uint32_t sb = (uint32_t)__cvta_generic_to_shared(smem);
    int* rows = (int*)smem;
    if (tid < 128) {
        int r = rowBase + tid;
        rows[tid] = (r < g_count[e]) ? g_list[e * NTOK + r] : -1;
    }
    __syncthreads();

    const __half* A = g_ah;
    const __half* B = g_W2h + (size_t)e * KTOT * NTOT + (size_t)nBase * KTOT;

    auto load_stage = [&](int st, int chunk) {
        const uint32_t stb = sb + 1024 + st * 32768;
        const int k0 = chunk * 64;
        #pragma unroll
        for (int t = 0; t < 4; ++t) {
            int c = tid + t * 256, r = c >> 3, q = c & 7;
            int s = rows[r]; if (s < 0) s = rows[0];
            size_t ro = (size_t)s * KTOT + k0 + q * 8;
            uint32_t so = sw128((uint32_t)(r * 128 + q * 16));
            cpa16(stb + so,         A + ro);
            cpa16(stb + 16384 + so, B + (size_t)r * KTOT + k0 + q * 8);
        }
    };

    const int lane = tid & 31, wid = tid >> 5;
    const int wm = (wid & 3) * 32, wn = (wid >> 2) * 64;
    const uint32_t aoff = (uint32_t)((wm + (lane & 15)) * 128 + (lane >> 4) * 16);
    const uint32_t boff0 = (uint32_t)((wn + ((lane >> 4) << 3) + (lane & 7)) * 128 +
                                      ((lane >> 3) & 1) * 16);

    float acc[2][8][4];
    #pragma unroll
    for (int i = 0; i < 2; ++i)
        #pragma unroll
        for (int j = 0; j < 8; ++j)
            #pragma unroll
            for (int k = 0; k < 4; ++k) acc[i][j][k] = 0.f;

    load_stage(0, 0); asm volatile("cp.async.commit_group;");
    load_stage(1, 1); asm volatile("cp.async.commit_group;");

    for (int it = 0; it < NCHUNK; ++it) {
        const int st = it % 3;
        asm volatile("cp.async.wait_group 1;");
        __syncthreads();
        const uint32_t stb = sb + 1024 + st * 32768;
        #pragma unroll
        for (int ks = 0; ks < 4; ++ks) {
            const uint32_t kb = ks * 32;
            uint32_t a[2][4], b[8][2];
            #pragma unroll
            for (int mi = 0; mi < 2; ++mi)
                ldmx4(a[mi], stb + sw128(aoff + mi * 16 * 128 + kb));
            #pragma unroll
            for (int nj = 0; nj < 4; ++nj) {
                uint32_t r[4];
                ldmx4(r, stb + 16384 + sw128(boff0 + nj * 16 * 128 + kb));
                b[nj*2][0] = r[0]; b[nj*2][1] = r[1];
                b[nj*2+1][0] = r[2]; b[nj*2+1][1] = r[3];
            }
            #pragma unroll
            for (int mi = 0; mi < 2; ++mi)
                #pragma unroll
                for (int nf = 0; nf < 8; ++nf)
                    mma_hf(acc[mi][nf], a[mi], b[nf]);
        }
        if (it + 2 < NCHUNK) load_stage((it + 2) % 3, it + 2);
        asm volatile("cp.async.commit_group;");
    }

    #pragma unroll
    for (int mi = 0; mi < 2; ++mi) {
        #pragma unroll
        for (int h = 0; h < 2; ++h) {
            const int rl = wm + mi * 16 + (lane >> 2) + h * 8;
            const int slot = rows[rl];
            if (slot < 0) continue;
            #pragma unroll
            for (int nf = 0; nf < 8; ++nf) {
                const int gc = nBase + wn + nf * 8 + (lane & 3) * 2;
                float2 o = make_float2(acc[mi][nf][h*2]   + b2[(size_t)e * DIM + gc],
                                       acc[mi][nf][h*2+1] + b2[(size_t)e * DIM + gc + 1]);
                *(float2*)(g_eo + (size_t)slot * DIM + gc) = o;
            }
        }
    }
}

// ---------------- head GEMM: fp16 single-pass, 3-stage pipe, 2 CTA/SM ----------------
__global__ void __launch_bounds__(256, 2) head_mma_kernel(const float* __restrict__ bias,
                                                          float* __restrict__ outp) {
    constexpr int NCHUNK = DIM / 64;
    extern __shared__ char smem[];
    const int tid = threadIdx.x;
    const int rowBase = blockIdx.x * 128, nBase = blockIdx.y * 128;
    const uint32_t sb = (uint32_t)__cvta_generic_to_shared(smem);

    auto load_stage = [&](int st, int chunk) {
        const uint32_t stb = sb + 1024 + st * 32768;
        const int k0 = chunk * 64;
        #pragma unroll
        for (int t = 0; t < 4; ++t) {
            int c = tid + t * 256, r = c >> 3, q = c & 7;
            uint32_t so = sw128((uint32_t)(r * 128 + q * 16));
            cpa16(stb + so,         g_ynh + (size_t)(rowBase + r) * DIM + k0 + q * 8);
            cpa16(stb + 16384 + so, g_Whf + (size_t)(nBase + r) * DIM + k0 + q * 8);
        }
    };

    const int lane = tid & 31, wid = tid >> 5;
    const int wm = (wid & 3) * 32, wn = (wid >> 2) * 64;
    const uint32_t aoff = (uint32_t)((wm + (lane & 15)) * 128 + (lane >> 4) * 16);
    const uint32_t boff0 = (uint32_t)((wn + ((lane >> 4) << 3) + (lane & 7)) * 128 +
                                      ((lane >> 3) & 1) * 16);

    float acc[2][8][4];
    #pragma unroll
    for (int i = 0; i < 2; ++i)
        #pragma unroll
        for (int j = 0; j < 8; ++j)
            #pragma unroll
            for (int k = 0; k < 4; ++k) acc[i][j][k] = 0.f;

    load_stage(0, 0); asm volatile("cp.async.commit_group;");
    load_stage(1, 1); asm volatile("cp.async.commit_group;");

    for (int it = 0; it < NCHUNK; ++it) {
        const int st = it % 3;
        asm volatile("cp.async.wait_group 1;");
        __syncthreads();
        const uint32_t stb = sb + 1024 + st * 32768;
        #pragma unroll
        for (int ks = 0; ks < 4; ++ks) {
            const uint32_t kb = ks * 32;
            uint32_t a[2][4], b[8][2];
            #pragma unroll
            for (int mi = 0; mi < 2; ++mi)
                ldmx4(a[mi], stb + sw128(aoff + mi * 16 * 128 + kb));
            #pragma unroll
            for (int nj = 0; nj < 4; ++nj) {
                uint32_t r[4];
                ldmx4(r, stb + 16384 + sw128(boff0 + nj * 16 * 128 + kb));
                b[nj*2][0] = r[0]; b[nj*2][1] = r[1];
                b[nj*2+1][0] = r[2]; b[nj*2+1][1] = r[3];
            }
            #pragma unroll
            for (int mi = 0; mi < 2; ++mi)
                #pragma unroll
                for (int nf = 0; nf < 8; ++nf)
                    mma_hf(acc[mi][nf], a[mi], b[nf]);
        }
        if (it + 2 < NCHUNK) load_stage((it + 2) % 3, it + 2);
        asm volatile("cp.async.commit_group;");
    }

    #pragma unroll
    for (int mi = 0; mi < 2; ++mi)
        #pragma unroll
        for (int h = 0; h < 2; ++h) {
            const int rl = wm + mi * 16 + (lane >> 2) + h * 8;
            #pragma unroll
            for (int nf = 0; nf < 8; ++nf) {
                const int gc = nBase + wn + nf * 8 + (lane & 3) * 2;
                float2 o = make_float2(acc[mi][nf][h*2]   + bias[gc],
                                       acc[mi][nf][h*2+1] + bias[gc+1]);
                *(float2*)(outp + (size_t)(rowBase + rl) * VOC + gc) = o;
            }
        }
}

// ---------------- combine gates + LayerNorm (-> yn fp16) ----------------
__global__ void combine_ln_kernel(const float* __restrict__ ln_g,
                                  const float* __restrict__ ln_b) {
    const int n = blockIdx.x, tid = threadIdx.x;
    const float* e0 = g_eo + (size_t)n * 2 * DIM;
    const float* e1 = e0 + DIM;
    const float tv0 = g_tv[n*2+0], tv1 = g_tv[n*2+1];
    float y[DIM / 256], s = 0.f, ss = 0.f;
    #pragma unroll
    for (int q = 0; q < DIM / 256; ++q) {
        int d = tid + q * 256;
        float v = fmaf(tv0, e0[d], tv1 * e1[d]);
        y[q] = v; s += v; ss = fmaf(v, v, ss);
    }
    __shared__ float rs[8], rss[8];
    #pragma unroll
    for (int o = 16; o > 0; o >>= 1) {
        s  += __shfl_xor_sync(0xffffffffu, s, o);
        ss += __shfl_xor_sync(0xffffffffu, ss, o);
    }
    const int w = tid >> 5, lane = tid & 31;
    if (lane == 0) { rs[w] = s; rss[w] = ss; }
    __syncthreads();
    if (w == 0) {
        s  = (lane < 8) ? rs[lane]  : 0.f;
        ss = (lane < 8) ? rss[lane] : 0.f;
        #pragma unroll
        for (int o = 4; o > 0; o >>= 1) {
            s  += __shfl_xor_sync(0xffffffffu, s, o);
            ss += __shfl_xor_sync(0xffffffffu, ss, o);
        }
        if (lane == 0) { rs[0] = s; rss[0] = ss; }
    }
    __syncthreads();
    const float mu  = rs[0] * (1.f / DIM);
    const float var = rss[0] * (1.f / DIM) - mu * mu;
    const float inv = rsqrtf(var + LN_EPS);
    #pragma unroll
    for (int q = 0; q < DIM / 256; ++q) {
        int d = tid + q * 256;
        float v = fmaf((y[q] - mu) * inv, ln_g[d], ln_b[d]);
        g_ynh[(size_t)n * DIM + d] = __float2half(v);
    }
}

// ---------------- launch ----------------
extern "C" void kernel_launch(void* const* d_in, const int* in_sizes, int n_in,
                              void* d_out, int out_size) {
    const int*   x       = (const int*)  d_in[0];
    const float* embed_W = (const float*)d_in[1];
    const float* gate_W  = (const float*)d_in[2];
    const float* gate_b  = (const float*)d_in[3];
    const float* W1      = (const float*)d_in[4];
    const float* b1      = (const float*)d_in[5];
    const float* W2      = (const float*)d_in[6];
    const float* b2      = (const float*)d_in[7];
    const float* ln_g    = (const float*)d_in[8];
    const float* ln_b    = (const float*)d_in[9];
    const float* head_W  = (const float*)d_in[10];
    const float* head_b  = (const float*)d_in[11];
    float* out = (float*)d_out;

    static int smem_set = 0;
    if (!smem_set) {
        cudaFuncSetAttribute(gemm1_fused_kernel,
                             cudaFuncAttributeMaxDynamicSharedMemorySize, GEMM_SMEM);
        cudaFuncSetAttribute(gemm2_kernel,
                             cudaFuncAttributeMaxDynamicSharedMemorySize, GEMM_SMEM);
        cudaFuncSetAttribute(head_mma_kernel,
                             cudaFuncAttributeMaxDynamicSharedMemorySize, GEMM_SMEM);
        smem_set = 1;
    }

    const long long need_idx = (long long)NTOK * VOC + (long long)NTOK * 2;
    int write_idx = ((long long)out_size >= need_idx) ? 1 : 0;

    reset_counts_kernel<<<1, 32>>>();
    embed_gate_w1_kernel<<<NTOK + W1T_BLOCKS, 256>>>(x, embed_W, gate_W, gate_b, W1,
                                                     out, write_idx);
    gemm1_fused_kernel<<<G1_BLOCKS + W2T_BLOCKS + CH_BLOCKS, 256, GEMM_SMEM>>>(
        b1, W2, (const float4*)head_W);
    gemm2_kernel<<<dim3(DIM / 128, NTOK / 128, NEXP), 256, GEMM_SMEM>>>(b2);
    combine_ln_kernel<<<NTOK, 256>>>(ln_g, ln_b);
    head_mma_kernel<<<dim3(NTOK / 128, VOC / 128), 256, GEMM_SMEM>>>(head_b, out);
}